// round 8
// baseline (speedup 1.0000x reference)
#include <cuda_runtime.h>

#define BB 256
#define TT 512
#define KK 128

// ---- scratch (no allocations allowed) ----
__device__ float g_v[(long)BB * TT * KK];   // 64MB: viterbi values per (b,t,k)
__device__ float g_transT[KK * KK];         // transT[c*K+j] = trans[j*K+c]
__device__ int   g_order[BB];               // batches sorted by length desc
__device__ float g_lognorm[BB];
__device__ float g_ll[BB];
__device__ int   g_correct[BB];
__device__ int   g_total[BB];

// ---- packed f32x2 helpers (sm_103a) ----
__device__ __forceinline__ unsigned long long f2pack(float a, float b) {
    unsigned long long r;
    asm("mov.b64 %0, {%1,%2};" : "=l"(r) : "f"(a), "f"(b));
    return r;
}
__device__ __forceinline__ void f2unpack(unsigned long long v, float& a, float& b) {
    asm("mov.b64 {%0,%1}, %2;" : "=f"(a), "=f"(b) : "l"(v));
}
__device__ __forceinline__ unsigned long long f2add(unsigned long long a, unsigned long long b) {
    unsigned long long r;
    asm("add.rn.f32x2 %0, %1, %2;" : "=l"(r) : "l"(a), "l"(b));
    return r;
}
__device__ __forceinline__ unsigned long long f2fma(unsigned long long a, unsigned long long b,
                                                    unsigned long long c) {
    unsigned long long r;
    asm("fma.rn.f32x2 %0, %1, %2, %3;" : "=l"(r) : "l"(a), "l"(b), "l"(c));
    return r;
}

// ============================================================
// Kernel 0a: transpose transitions (tiny).
// ============================================================
__global__ void transpose_kernel(const float* __restrict__ trans)
{
    int c = blockIdx.x, j = threadIdx.x;
    g_transT[c * KK + j] = trans[j * KK + c];
}

// ============================================================
// Kernel 0b: rank-sort batches by length descending (LPT).
// ============================================================
__global__ void sort_kernel(const int* __restrict__ lengths)
{
    __shared__ int keys[BB];
    int b = threadIdx.x;
    int key = (lengths[b] << 8) | (BB - 1 - b);
    keys[b] = key;
    __syncthreads();
    int r = 0;
    #pragma unroll 8
    for (int j = 0; j < BB; j++) r += (keys[j] > key);
    g_order[r] = b;
}

// ============================================================
// Kernel 1: fused scans with early exit at t = len.
// Blocks [0,256) = Viterbi forward (packed adds + scalar max),
// blocks [256,512) = CRF forward (exp-domain logsumexp).
// ============================================================
__global__ __launch_bounds__(128)
void crf_scan_kernel(const float* __restrict__ emissions,
                     const int*   __restrict__ lengths,
                     const float* __restrict__ trans)
{
    __shared__ ulonglong2 bufP[2][KK / 4];   // packed state vector (double buffer)
    __shared__ float      redS[2][4];

    const int k    = threadIdx.x;
    const int role = (blockIdx.x >= BB);
    const int b    = g_order[role ? (blockIdx.x - BB) : blockIdx.x];
    const int len  = lengths[b];
    const float* em = emissions + (long)b * TT * KK;
    const int wid = k >> 5, lane = k & 31;

    if (!role) {
        // -------- Viterbi forward: packed adds, scalar max, t < len --------
        unsigned long long trp[KK / 2];      // packed transition column k
        #pragma unroll
        for (int m = 0; m < KK / 2; m++)
            trp[m] = f2pack(trans[(2 * m) * KK + k], trans[(2 * m + 1) * KK + k]);

        float* vglob = g_v + (long)b * TT * KK;

        float v = em[k];                     // t = 0
        vglob[k] = v;
        int buf = 0;
        ((float*)bufP[0])[k] = v;
        __syncthreads();

        float emit = em[KK + k];             // prefetch t = 1
        for (int t = 1; t < len; t++) {
            float emit_next = (t + 1 < TT) ? em[(t + 1) * KK + k] : 0.0f;

            float b0 = -3.4e38f, b1 = -3.4e38f, b2 = -3.4e38f, b3 = -3.4e38f;
            #pragma unroll
            for (int jj = 0; jj < KK / 4; jj++) {
                ulonglong2 q = bufP[buf][jj];
                float x0, x1, x2, x3;
                f2unpack(f2add(q.x, trp[2 * jj]),     x0, x1);
                f2unpack(f2add(q.y, trp[2 * jj + 1]), x2, x3);
                b0 = fmaxf(b0, x0); b1 = fmaxf(b1, x1);
                b2 = fmaxf(b2, x2); b3 = fmaxf(b3, x3);
            }
            v = fmaxf(fmaxf(b0, b1), fmaxf(b2, b3)) + emit;
            vglob[t * KK + k] = v;

            ((float*)bufP[buf ^ 1])[k] = v;
            __syncthreads();
            buf ^= 1;
            emit = emit_next;
        }
    } else {
        // -------- CRF forward (log partition), exp-domain, t < len --------
        unsigned long long Ep[KK / 2];       // packed exp(transition) column k
        #pragma unroll
        for (int m = 0; m < KK / 2; m++)
            Ep[m] = f2pack(__expf(trans[(2 * m) * KK + k]),
                           __expf(trans[(2 * m + 1) * KK + k]));

        float alpha = em[k];
        int buf = 1;                         // first write goes to nb = 0

        float emit = em[KK + k];
        for (int t = 1; t < len; t++) {
            float emit_next = (t + 1 < TT) ? em[(t + 1) * KK + k] : 0.0f;

            // per-warp max of alpha
            float mw = alpha;
            #pragma unroll
            for (int o = 16; o > 0; o >>= 1)
                mw = fmaxf(mw, __shfl_xor_sync(0xffffffffu, mw, o));

            int nb = buf ^ 1;
            float p = __expf(alpha - mw);
            ((float*)bufP[nb])[k] = p;
            if (lane == 0) redS[nb][wid] = mw;
            __syncthreads();

            float m0 = redS[nb][0], m1 = redS[nb][1];
            float m2 = redS[nb][2], m3 = redS[nb][3];
            float m = fmaxf(fmaxf(m0, m1), fmaxf(m2, m3));

            // grouped packed dot: group g = warp g's p's (rescaled after)
            unsigned long long acc0 = f2pack(0.f, 0.f), acc1 = acc0,
                               acc2 = acc0, acc3 = acc0;
            #pragma unroll
            for (int jj = 0; jj < 8; jj++) {
                ulonglong2 q = bufP[nb][jj];
                acc0 = f2fma(q.x, Ep[2 * jj],     acc0);
                acc0 = f2fma(q.y, Ep[2 * jj + 1], acc0);
            }
            #pragma unroll
            for (int jj = 8; jj < 16; jj++) {
                ulonglong2 q = bufP[nb][jj];
                acc1 = f2fma(q.x, Ep[2 * jj],     acc1);
                acc1 = f2fma(q.y, Ep[2 * jj + 1], acc1);
            }
            #pragma unroll
            for (int jj = 16; jj < 24; jj++) {
                ulonglong2 q = bufP[nb][jj];
                acc2 = f2fma(q.x, Ep[2 * jj],     acc2);
                acc2 = f2fma(q.y, Ep[2 * jj + 1], acc2);
            }
            #pragma unroll
            for (int jj = 24; jj < 32; jj++) {
                ulonglong2 q = bufP[nb][jj];
                acc3 = f2fma(q.x, Ep[2 * jj],     acc3);
                acc3 = f2fma(q.y, Ep[2 * jj + 1], acc3);
            }
            float lo, hi, s;
            f2unpack(acc0, lo, hi); s = __expf(m0 - m) * (lo + hi);
            f2unpack(acc1, lo, hi); s = fmaf(__expf(m1 - m), lo + hi, s);
            f2unpack(acc2, lo, hi); s = fmaf(__expf(m2 - m), lo + hi, s);
            f2unpack(acc3, lo, hi); s = fmaf(__expf(m3 - m), lo + hi, s);

            alpha = m + __logf(s) + emit;
            buf = nb;
            emit = emit_next;
        }

        // final logsumexp over k
        __syncthreads();
        float mw = alpha;
        #pragma unroll
        for (int o = 16; o > 0; o >>= 1)
            mw = fmaxf(mw, __shfl_xor_sync(0xffffffffu, mw, o));
        if (lane == 0) redS[0][wid] = mw;
        __syncthreads();
        float m = fmaxf(fmaxf(redS[0][0], redS[0][1]), fmaxf(redS[0][2], redS[0][3]));
        float p = __expf(alpha - m);
        #pragma unroll
        for (int o = 16; o > 0; o >>= 1)
            p += __shfl_xor_sync(0xffffffffu, p, o);
        __syncthreads();
        if (lane == 0) redS[0][wid] = p;
        __syncthreads();
        if (k == 0) {
            float s = redS[0][0] + redS[0][1] + redS[0][2] + redS[0][3];
            g_lognorm[b] = m + __logf(s);
        }
    }
}

// ============================================================
// Kernel 2: backtrack by argmax recomputation along the path.
// 1 warp/batch. Deep (8) register-ring prefetch of v rows,
// transT warmed into L1, redux-based argmax (short chain).
// ============================================================
__global__ __launch_bounds__(32)
void crf_backward_kernel(const float* __restrict__ emissions,
                         const int*   __restrict__ tag_ids,
                         const int*   __restrict__ lengths,
                         float*       __restrict__ out)
{
    __shared__ int tagS[TT];

    const int b    = blockIdx.x;
    const int lane = threadIdx.x;
    const int len  = lengths[b];
    const int t0   = len - 1;
    const float* vb = g_v + (long)b * TT * KK;

    // ---- warm transT into L1 (independent loads, MLP-overlapped) ----
    float warm0 = 0.f, warm1 = 0.f, warm2 = 0.f, warm3 = 0.f;
    const float4* tT4 = (const float4*)g_transT;
    #pragma unroll 4
    for (int i = lane; i < KK * KK / 4; i += 32) {
        float4 w4 = __ldg(tT4 + i);
        warm0 += w4.x; warm1 += w4.y; warm2 += w4.z; warm3 += w4.w;
    }
    if (warm0 + warm1 + warm2 + warm3 == 1.2345e38f)
        out[0] = warm0;   // unreachable; keeps warm loads alive

    // ---- last_tag = argmax(v at row len-1), first index on ties ----
    float4 q = __ldg((const float4*)(vb + (long)t0 * KK) + lane);
    float bv = q.x; int bi = 0;
    if (q.y > bv) { bv = q.y; bi = 1; }
    if (q.z > bv) { bv = q.z; bi = 2; }
    if (q.w > bv) { bv = q.w; bi = 3; }
    unsigned key = __float_as_uint(bv);
    key ^= ((unsigned)((int)key >> 31)) | 0x80000000u;   // ordered-uint map
    unsigned mk = __reduce_max_sync(0xffffffffu, key);
    unsigned cand = (key == mk) ? (unsigned)((lane << 2) | bi) : 0xFFFFu;
    int cur = (int)__reduce_min_sync(0xffffffffu, cand);

    // fill tail [t0, TT) with last_tag (matches identity backpointers)
    for (int t = t0 + lane; t < TT; t += 32) tagS[t] = cur;

    // ---- deep prefetch ring: slot u holds row (chunk - u - 1) ----
    float4 ring[8];
    #pragma unroll
    for (int u = 0; u < 8; u++) {
        int r = t0 - 1 - u; if (r < 0) r = 0;
        ring[u] = __ldcs((const float4*)(vb + (long)r * KK) + lane);
    }

    for (int tcb = t0; tcb >= 1; tcb -= 8) {
        #pragma unroll
        for (int u = 0; u < 8; u++) {
            int t = tcb - u;
            if (t >= 1) {
                float4 vrow = ring[u];
                int nr = t - 9; if (nr < 0) nr = 0;
                ring[u] = __ldcs((const float4*)(vb + (long)nr * KK) + lane);

                float4 tc4 = __ldg((const float4*)(g_transT + (cur << 7)) + lane);
                float w0 = vrow.x + tc4.x, w1 = vrow.y + tc4.y;
                float w2 = vrow.z + tc4.z, w3 = vrow.w + tc4.w;
                float lb = w0; int li = 0;
                if (w1 > lb) { lb = w1; li = 1; }
                if (w2 > lb) { lb = w2; li = 2; }
                if (w3 > lb) { lb = w3; li = 3; }
                unsigned k2 = __float_as_uint(lb);
                k2 ^= ((unsigned)((int)k2 >> 31)) | 0x80000000u;
                unsigned m2 = __reduce_max_sync(0xffffffffu, k2);
                unsigned c2 = (k2 == m2) ? (unsigned)((lane << 2) | li) : 0xFFFFu;
                cur = (int)__reduce_min_sync(0xffffffffu, c2);
                if (lane == 0) tagS[t - 1] = cur;
            }
        }
    }
    __syncwarp();

    // ---- decoded output + gold-path score + accuracy ----
    float sc = 0.f;
    int correct = 0;
    for (int t = lane; t < TT; t += 32) {
        int tg = tagS[t];
        out[1 + b * TT + t] = (float)tg;
        int ref = __ldg(tag_ids + b * TT + t);
        if (t < len) {
            correct += (ref == tg);
            sc += __ldg(emissions + ((long)b * TT + t) * KK + ref);
            if (t >= 1) {
                int prev = __ldg(tag_ids + b * TT + t - 1);
                sc += __ldg(g_transT + (ref << 7) + prev);   // trans[prev][ref]
            }
        }
    }
    #pragma unroll
    for (int o = 16; o > 0; o >>= 1) {
        sc      += __shfl_xor_sync(0xffffffffu, sc, o);
        correct += __shfl_xor_sync(0xffffffffu, correct, o);
    }
    if (lane == 0) {
        g_ll[b]      = sc - g_lognorm[b];
        g_correct[b] = correct;
        g_total[b]   = len;
    }
}

// ============================================================
// Kernel 3: finalize loss + accuracy (deterministic).
// ============================================================
__global__ void crf_finalize_kernel(float* __restrict__ out)
{
    __shared__ float llS[BB];
    __shared__ int   cS[BB];
    __shared__ int   tS[BB];
    int k = threadIdx.x;   // 256 threads
    llS[k] = g_ll[k]; cS[k] = g_correct[k]; tS[k] = g_total[k];
    __syncthreads();
    if (k == 0) {
        float s = 0.f; int c = 0, t = 0;
        for (int i = 0; i < BB; i++) { s += llS[i]; c += cS[i]; t += tS[i]; }
        out[0] = -s / (float)BB;
        out[1 + BB * TT] = (float)c / (float)t;
    }
}

extern "C" void kernel_launch(void* const* d_in, const int* in_sizes, int n_in,
                              void* d_out, int out_size)
{
    const float* emissions = (const float*)d_in[0];   // (256,512,128) f32
    const int*   tag_ids   = (const int*)d_in[1];     // (256,512) i32
    const int*   lengths   = (const int*)d_in[2];     // (256,) i32
    const float* trans     = (const float*)d_in[3];   // (128,128) f32
    float* out = (float*)d_out;                       // [loss, decoded(B*T), acc]

    sort_kernel<<<1, BB>>>(lengths);
    transpose_kernel<<<KK, KK>>>(trans);
    crf_scan_kernel<<<2 * BB, 128>>>(emissions, lengths, trans);
    crf_backward_kernel<<<BB, 32>>>(emissions, tag_ids, lengths, out);
    crf_finalize_kernel<<<1, BB>>>(out);
}